// round 5
// baseline (speedup 1.0000x reference)
#include <cuda_runtime.h>
#include <cstdint>

#define Bq 16
#define Nq 2048
#define Cq 3
#define Kq 100
#define THREADS 512
#define PER (Nq / THREADS)   // 4 contiguous sorted positions per thread
#define NWORD (Nq / 64)      // 32 bitmap words
#define NTILE (Nq / 64)      // 32 tiles of 64 sorted positions
#define KCAP 128             // kept-list capacity (kept is capped at Kq=100)
#define NEGV (-1e9f)

typedef unsigned long long u64;

// float -> key: ascending-uint == DESCENDING-float order.
__device__ __forceinline__ unsigned fkey_desc(float f) {
    unsigned u = __float_as_uint(f);
    u = (u & 0x80000000u) ? ~u : (u | 0x80000000u);
    return ~u;
}
// lossless inverse
__device__ __forceinline__ float key_to_score(unsigned k) {
    unsigned u = ~k;
    u = (u & 0x80000000u) ? (u & 0x7fffffffu) : ~u;
    return __uint_as_float(u);
}

__global__ void __launch_bounds__(THREADS)
roiheads_kernel(const float* __restrict__ logit,   // [B,N,3]
                const float* __restrict__ reg,     // [B,N,6]
                const float* __restrict__ prop,    // [B,N,2]
                const int*   __restrict__ ishape,  // scalar
                float*       __restrict__ out)     // [B,2,K,3]
{
    __shared__ u64    keys[Nq];          // sorted (scoreKey<<32 | idx)
    __shared__ float2 lohi[Nq];          // idx-indexed clipped boxes
    __shared__ float  keptLo[KCAP], keptHi[KCAP];
    __shared__ unsigned char suppFlag[64];
    __shared__ u64    alive[NWORD];
    __shared__ int    sKeptTotal, sStop, sStopT;
    __shared__ int    wp[NWORD + 1];

    const int b    = blockIdx.x >> 1;
    const int c    = blockIdx.x & 1;
    const int cls  = c + 1;
    const int tid  = threadIdx.x;
    const int lane = tid & 31;
    const int base = tid * PER;          // first owned sorted position

    int ib = ishape[0];
    float img = (ib > 0 && ib < (1 << 24)) ? (float)ib : __int_as_float(ib);

    if (tid < NWORD) alive[tid] = 0ull;
    if (tid == 0) { sKeptTotal = 0; sStop = 0; sStopT = NTILE - 1; }

    // ---------- Phase 1: softmax + decode + clip + mask -> keys in regs ----------
    u64 v[PER];
    {
        const float4* lgv = (const float4*)(logit + ((size_t)b * Nq + base) * Cq);
        float4 L0 = lgv[0], L1 = lgv[1], L2 = lgv[2];
        const float4* ppv = (const float4*)(prop + ((size_t)b * Nq + base) * 2);
        float4 P0 = ppv[0], P1 = ppv[1];
        float lg[12] = {L0.x,L0.y,L0.z,L0.w,L1.x,L1.y,L1.z,L1.w,L2.x,L2.y,L2.z,L2.w};
        float pr[8]  = {P0.x,P0.y,P0.z,P0.w,P1.x,P1.y,P1.z,P1.w};

        #pragma unroll
        for (int r = 0; r < PER; r++) {
            int j = base + r;
            float l0 = lg[r*3+0], l1 = lg[r*3+1], l2 = lg[r*3+2];
            float m  = fmaxf(l0, fmaxf(l1, l2));
            float e0 = expf(l0 - m), e1 = expf(l1 - m), e2 = expf(l2 - m);
            float s  = ((cls == 1) ? e1 : e2) / (e0 + e1 + e2);

            const float2 dd = *(const float2*)(reg + ((size_t)b * Nq + j) * (2 * Cq) + 2 * cls);
            float dx = dd.x;
            float dw = fminf(dd.y, 4.0f);

            float p0 = pr[r*2+0], p1 = pr[r*2+1];
            float w   = p1 - p0;
            float ctr = p0 + 0.5f * w;
            float pc  = dx * w + ctr;
            float pw  = expf(dw) * w;
            float lo  = fminf(fmaxf(pc - 0.5f * pw, 0.0f), img);
            float hi  = fminf(fmaxf(pc + 0.5f * pw, 0.0f), img);

            bool  valid = ((hi - lo) >= 10.0f) && (s >= 0.05f);
            float ms    = valid ? s : NEGV;

            lohi[j] = make_float2(lo, hi);
            v[r] = ((u64)fkey_desc(ms) << 32) | (unsigned)j;
        }
    }

    // ---------- Phase 2: bitonic sort; smem only for strides >= 128 ----------
    for (int k = 2; k <= Nq; k <<= 1) {
        int j2 = k >> 1;
        if (j2 >= 128) {
            #pragma unroll
            for (int r = 0; r < PER; r++) keys[base + r] = v[r];
            __syncthreads();
            for (; j2 >= 128; j2 >>= 1) {
                #pragma unroll
                for (int rr = 0; rr < PER; rr++) {
                    int i  = tid + rr * THREADS;
                    int ix = i ^ j2;
                    if (ix > i) {
                        bool up = ((i & k) == 0);
                        u64 a = keys[i], bb = keys[ix];
                        if ((a > bb) == up) { keys[i] = bb; keys[ix] = a; }
                    }
                }
                __syncthreads();
            }
            #pragma unroll
            for (int r = 0; r < PER; r++) v[r] = keys[base + r];
        }
        // warp-local strides 64..4 via shuffle
        for (; j2 >= 4; j2 >>= 1) {
            int ld = j2 >> 2;
            #pragma unroll
            for (int r = 0; r < PER; r++) {
                u64 other = __shfl_xor_sync(0xffffffffu, v[r], ld);
                int i = base + r;
                bool up    = ((i & k)  == 0);
                bool lower = ((i & j2) == 0);
                bool tmin  = (up == lower);
                u64 mn = (v[r] < other) ? v[r] : other;
                u64 mx = (v[r] < other) ? other : v[r];
                v[r] = tmin ? mn : mx;
            }
        }
        // register-local strides 2,1
        #pragma unroll
        for (int j2r = 2; j2r >= 1; j2r >>= 1) {
            if (j2r < k) {
                #pragma unroll
                for (int r = 0; r < PER; r++) {
                    int rx = r ^ j2r;
                    if (rx > r) {
                        bool up = (((base + r) & k) == 0);
                        u64 a = v[r], bb = v[rx];
                        if ((a > bb) == up) { v[r] = bb; v[rx] = a; }
                    }
                }
            }
        }
    }

    // ---------- Phase 3: spill sorted keys; build initial validity bitmap ----------
    unsigned myValid = 0;
    #pragma unroll
    for (int r = 0; r < PER; r++) {
        keys[base + r] = v[r];
        if (key_to_score((unsigned)(v[r] >> 32)) > 0.5f * NEGV)
            myValid |= (1u << r);
    }
    if (myValid)
        atomicOr(&alive[tid >> 4], (u64)myValid << ((tid & 15) * PER));
    __syncthreads();

    // ---------- Phase 4: lazy-suppression tile NMS ----------
    const int      fi   = tid >> 3;           // box within tile (0..63)
    const int      fsl  = tid & 7;            // slice of kept-list
    const unsigned grp  = 0xffu << ((tid & 31) & ~7);

    for (int t = 0; t < NTILE; t++) {
        u64 at0 = alive[t];                   // consistent: barrier ended prev iter
        if (at0 == 0ull) continue;

        const int T0 = sKeptTotal;

        // A: filter tile boxes against global kept list (8 threads / box)
        bool kill = false;
        if ((at0 >> fi) & 1) {
            u64 key = keys[t * 64 + fi];
            float2 lh = lohi[(int)(key & 0xffffffffu)];
            float lo = lh.x, hi = lh.y, wb = hi - lo;
            for (int s = fsl; s < T0; s += 8) {
                float pl = keptLo[s], ph = keptHi[s];
                float inter = fminf(ph, hi) - fmaxf(pl, lo);
                if (inter > 0.0f) {
                    float uni = (ph - pl) + wb - inter;
                    if (inter / fmaxf(uni, 1e-8f) > 0.5f) { kill = true; break; }
                }
            }
        }
        unsigned anyk = __any_sync(grp, kill);
        if (fsl == 0) suppFlag[fi] = (unsigned char)(anyk ? 1 : 0);
        __syncthreads();

        // B: warp 0 greedy on surviving boxes (2 boxes / lane), capped at Kq kept
        if (tid < 32) {
            u64 k0 = keys[t * 64 + lane];
            u64 k1 = keys[t * 64 + lane + 32];
            float2 a0 = lohi[(int)(k0 & 0xffffffffu)];
            float2 a1 = lohi[(int)(k1 & 0xffffffffu)];
            float lo0 = a0.x, hi0 = a0.y, lo1 = a1.x, hi1 = a1.y;

            unsigned s0 = __ballot_sync(0xffffffffu, suppFlag[lane] != 0);
            unsigned s1 = __ballot_sync(0xffffffffu, suppFlag[lane + 32] != 0);
            u64 rest = at0 & ~(((u64)s1 << 32) | (u64)s0);

            u64 kept = 0;
            int kt = T0;
            while (rest && kt < Kq) {
                int pos = __ffsll((long long)rest) - 1;
                kept |= (1ull << pos);
                float candL = (pos & 32) ? lo1 : lo0;
                float candH = (pos & 32) ? hi1 : hi0;
                float pl = __shfl_sync(0xffffffffu, candL, pos & 31);
                float ph = __shfl_sync(0xffffffffu, candH, pos & 31);
                float pw = ph - pl;
                bool q0 = false, q1 = false;
                {
                    float inter = fminf(ph, hi0) - fmaxf(pl, lo0);
                    if (inter > 0.0f) {
                        float uni = pw + (hi0 - lo0) - inter;
                        q0 = inter / fmaxf(uni, 1e-8f) > 0.5f;
                    }
                    inter = fminf(ph, hi1) - fmaxf(pl, lo1);
                    if (inter > 0.0f) {
                        float uni = pw + (hi1 - lo1) - inter;
                        q1 = inter / fmaxf(uni, 1e-8f) > 0.5f;
                    }
                }
                unsigned b0 = __ballot_sync(0xffffffffu, q0);
                unsigned b1 = __ballot_sync(0xffffffffu, q1);
                rest &= ~(((u64)b1 << 32) | (u64)b0);
                rest = (pos < 63) ? (rest & (~0ull << (pos + 1))) : 0ull;
                if (lane == 0) { keptLo[kt] = pl; keptHi[kt] = ph; }
                kt++;
            }
            if (lane == 0) {
                alive[t] = kept;
                sKeptTotal = kt;
                if (kt >= Kq) { sStop = 1; sStopT = t; }
            }
        }
        __syncthreads();
        if (sStop) break;     // exactly K kept found; later tiles cannot matter
    }

    // Tiles past the stop point contribute nothing
    if (tid < NWORD && tid > sStopT) alive[tid] = 0ull;
    __syncthreads();

    // ---------- Phase 5: ranks + emit top-K with NEG padding ----------
    if (tid == 0) {
        int acc = 0;
        #pragma unroll
        for (int w = 0; w < NWORD; w++) { wp[w] = acc; acc += __popcll(alive[w]); }
        wp[NWORD] = acc;
    }
    __syncthreads();
    const int T = wp[NWORD];
    float* o = out + ((size_t)(b * 2 + c)) * Kq * 3;

    const u64 aw = alive[tid >> 4];
    #pragma unroll
    for (int r = 0; r < PER; r++) {
        int p = base + r;
        int bit = p & 63;
        u64 lowmask = (bit == 0) ? 0ull : ((1ull << bit) - 1ull);
        int  kr   = wp[p >> 6] + __popcll(aw & lowmask);
        bool kept = (aw >> bit) & 1ull;
        if (kept) {
            if (kr < Kq) {
                u64 key = keys[p];
                float2 lh = lohi[(int)(key & 0xffffffffu)];
                o[kr * 3 + 0] = lh.x;
                o[kr * 3 + 1] = lh.y;
                o[kr * 3 + 2] = key_to_score((unsigned)(key >> 32));
            }
        } else {
            int nr = p - kr;                       // non-kept rank (lowest pos first)
            if (T < Kq && nr < Kq - T) {
                u64 key = keys[p];
                float2 lh = lohi[(int)(key & 0xffffffffu)];
                int slot = T + nr;
                o[slot * 3 + 0] = lh.x;
                o[slot * 3 + 1] = lh.y;
                o[slot * 3 + 2] = NEGV;
            }
        }
    }
}

extern "C" void kernel_launch(void* const* d_in, const int* in_sizes, int n_in,
                              void* d_out, int out_size)
{
    const float* logit  = (const float*)d_in[0];   // [16,2048,3]
    const float* reg    = (const float*)d_in[1];   // [16,2048,6]
    const float* prop   = (const float*)d_in[2];   // [16,2048,2]
    const int*   ishape = (const int*)d_in[3];     // scalar
    float* out = (float*)d_out;                    // [16,2,100,3]

    roiheads_kernel<<<Bq * (Cq - 1), THREADS>>>(logit, reg, prop, ishape, out);
}

// round 6
// speedup vs baseline: 1.2242x; 1.2242x over previous
#include <cuda_runtime.h>
#include <cstdint>

#define Bq 16
#define Nq 2048
#define Cq 3
#define Kq 100
#define THREADS 512
#define PER (Nq / THREADS)   // 4 contiguous sorted positions per thread
#define NWORD (Nq / 64)      // 32 bitmap words
#define NTILE (Nq / 64)      // 32 tiles of 64 sorted positions
#define KCAP 112             // kept list capped at Kq
#define NEGV (-1e9f)

typedef unsigned long long u64;

// float -> key: ascending-uint == DESCENDING-float order.
__device__ __forceinline__ unsigned fkey_desc(float f) {
    unsigned u = __float_as_uint(f);
    u = (u & 0x80000000u) ? ~u : (u | 0x80000000u);
    return ~u;
}
// lossless inverse
__device__ __forceinline__ float key_to_score(unsigned k) {
    unsigned u = ~k;
    u = (u & 0x80000000u) ? (u & 0x7fffffffu) : ~u;
    return __uint_as_float(u);
}

__global__ void __launch_bounds__(THREADS)
roiheads_kernel(const float* __restrict__ logit,   // [B,N,3]
                const float* __restrict__ reg,     // [B,N,6]
                const float* __restrict__ prop,    // [B,N,2]
                const int*   __restrict__ ishape,  // scalar
                float*       __restrict__ out)     // [B,2,K,3]
{
    __shared__ u64    keys[Nq];          // sorted (scoreKey<<32 | idx)
    __shared__ float2 lohi[Nq];          // idx-indexed clipped boxes
    __shared__ float  keptLo[KCAP], keptHi[KCAP];
    __shared__ u64    alive[NWORD];
    __shared__ int    sDLo[2], sDHi[2];  // double-buffered delta bounds
    __shared__ int    sStop, sStopT;
    __shared__ int    wp[NWORD + 1];

    const int b      = blockIdx.x >> 1;
    const int c      = blockIdx.x & 1;
    const int cls    = c + 1;
    const int tid    = threadIdx.x;
    const int lane   = tid & 31;
    const int base   = tid * PER;        // first owned sorted position
    const int myTile = tid >> 4;         // 16 threads own one 64-slot tile

    int ib = ishape[0];
    float img = (ib > 0 && ib < (1 << 24)) ? (float)ib : __int_as_float(ib);

    if (tid < NWORD) alive[tid] = 0ull;
    if (tid == 0) { sDLo[0] = 0; sDHi[0] = 0; sStop = 0; sStopT = NTILE - 1; }

    // ---------- Phase 1: softmax + decode + clip + mask -> keys in regs ----------
    u64 v[PER];
    {
        const float4* lgv = (const float4*)(logit + ((size_t)b * Nq + base) * Cq);
        float4 L0 = lgv[0], L1 = lgv[1], L2 = lgv[2];
        const float4* ppv = (const float4*)(prop + ((size_t)b * Nq + base) * 2);
        float4 P0 = ppv[0], P1 = ppv[1];
        float lg[12] = {L0.x,L0.y,L0.z,L0.w,L1.x,L1.y,L1.z,L1.w,L2.x,L2.y,L2.z,L2.w};
        float pr[8]  = {P0.x,P0.y,P0.z,P0.w,P1.x,P1.y,P1.z,P1.w};

        #pragma unroll
        for (int r = 0; r < PER; r++) {
            int j = base + r;
            float l0 = lg[r*3+0], l1 = lg[r*3+1], l2 = lg[r*3+2];
            float m  = fmaxf(l0, fmaxf(l1, l2));
            float e0 = expf(l0 - m), e1 = expf(l1 - m), e2 = expf(l2 - m);
            float s  = ((cls == 1) ? e1 : e2) / (e0 + e1 + e2);

            const float2 dd = *(const float2*)(reg + ((size_t)b * Nq + j) * (2 * Cq) + 2 * cls);
            float dx = dd.x;
            float dw = fminf(dd.y, 4.0f);

            float p0 = pr[r*2+0], p1 = pr[r*2+1];
            float w   = p1 - p0;
            float ctr = p0 + 0.5f * w;
            float pc  = dx * w + ctr;
            float pw  = expf(dw) * w;
            float lo  = fminf(fmaxf(pc - 0.5f * pw, 0.0f), img);
            float hi  = fminf(fmaxf(pc + 0.5f * pw, 0.0f), img);

            bool  valid = ((hi - lo) >= 10.0f) && (s >= 0.05f);
            float ms    = valid ? s : NEGV;

            lohi[j] = make_float2(lo, hi);
            v[r] = ((u64)fkey_desc(ms) << 32) | (unsigned)j;
        }
    }

    // ---------- Phase 2: bitonic sort; smem only for strides >= 128 ----------
    for (int k = 2; k <= Nq; k <<= 1) {
        int j2 = k >> 1;
        if (j2 >= 128) {
            #pragma unroll
            for (int r = 0; r < PER; r++) keys[base + r] = v[r];
            __syncthreads();
            for (; j2 >= 128; j2 >>= 1) {
                #pragma unroll
                for (int rr = 0; rr < PER; rr++) {
                    int i  = tid + rr * THREADS;
                    int ix = i ^ j2;
                    if (ix > i) {
                        bool up = ((i & k) == 0);
                        u64 a = keys[i], bb = keys[ix];
                        if ((a > bb) == up) { keys[i] = bb; keys[ix] = a; }
                    }
                }
                __syncthreads();
            }
            #pragma unroll
            for (int r = 0; r < PER; r++) v[r] = keys[base + r];
        }
        // warp-local strides 64..4 via shuffle
        for (; j2 >= 4; j2 >>= 1) {
            int ld = j2 >> 2;
            #pragma unroll
            for (int r = 0; r < PER; r++) {
                u64 other = __shfl_xor_sync(0xffffffffu, v[r], ld);
                int i = base + r;
                bool up    = ((i & k)  == 0);
                bool lower = ((i & j2) == 0);
                bool tmin  = (up == lower);
                u64 mn = (v[r] < other) ? v[r] : other;
                u64 mx = (v[r] < other) ? other : v[r];
                v[r] = tmin ? mn : mx;
            }
        }
        // register-local strides 2,1
        #pragma unroll
        for (int j2r = 2; j2r >= 1; j2r >>= 1) {
            if (j2r < k) {
                #pragma unroll
                for (int r = 0; r < PER; r++) {
                    int rx = r ^ j2r;
                    if (rx > r) {
                        bool up = (((base + r) & k) == 0);
                        u64 a = v[r], bb = v[rx];
                        if ((a > bb) == up) { v[r] = bb; v[rx] = a; }
                    }
                }
            }
        }
    }

    // ---------- Phase 3: spill keys; owners cache boxes; build alive bitmap ----------
    float myLo[PER], myHi[PER];
    unsigned myAlive = 0;
    #pragma unroll
    for (int r = 0; r < PER; r++) {
        keys[base + r] = v[r];
        int idx = (int)(v[r] & 0xffffffffu);
        float2 lh = lohi[idx];
        myLo[r] = lh.x;
        myHi[r] = lh.y;
        if (key_to_score((unsigned)(v[r] >> 32)) > 0.5f * NEGV)
            myAlive |= (1u << r);
    }
    if (myAlive)
        atomicOr(&alive[tid >> 4], (u64)myAlive << ((tid & 15) * PER));
    __syncthreads();

    // ---------- Phase 4: pipelined tile NMS (1 barrier / tile) ----------
    // warp0 persistent state: tile-t boxes (2 per lane) + uniform kept total
    float glo0 = 0.f, ghi0 = 0.f, glo1 = 0.f, ghi1 = 0.f;
    int kt = 0;
    if (tid < 32) {
        u64 k0 = keys[lane];
        u64 k1 = keys[lane + 32];
        float2 a0 = lohi[(int)(k0 & 0xffffffffu)];
        float2 a1 = lohi[(int)(k1 & 0xffffffffu)];
        glo0 = a0.x; ghi0 = a0.y; glo1 = a1.x; ghi1 = a1.y;
    }

    for (int t = 0; t < NTILE; t++) {
        if (tid < 32) {
            u64 at = alive[t];
            // urgent: apply previous tile's kept delta to this tile's boxes
            const int dLo = sDLo[t & 1], dHi = sDHi[t & 1];
            if (at != 0ull && dHi > dLo) {
                bool q0 = false, q1 = false;
                float w0 = ghi0 - glo0, w1 = ghi1 - glo1;
                for (int s = dLo; s < dHi; s++) {
                    float pl = keptLo[s], ph = keptHi[s];
                    float pw = ph - pl;
                    float i0 = fminf(ph, ghi0) - fmaxf(pl, glo0);
                    if (i0 > 0.0f) {
                        float uni = pw + w0 - i0;
                        q0 |= (i0 / fmaxf(uni, 1e-8f) > 0.5f);
                    }
                    float i1 = fminf(ph, ghi1) - fmaxf(pl, glo1);
                    if (i1 > 0.0f) {
                        float uni = pw + w1 - i1;
                        q1 |= (i1 / fmaxf(uni, 1e-8f) > 0.5f);
                    }
                }
                unsigned b0 = __ballot_sync(0xffffffffu, q0);
                unsigned b1 = __ballot_sync(0xffffffffu, q1);
                at &= ~(((u64)b1 << 32) | (u64)b0);
            }
            // greedy over the tile, capped at Kq kept total
            const int T0 = kt;
            u64 kept = 0;
            while (at && kt < Kq) {
                int pos = __ffsll((long long)at) - 1;
                kept |= (1ull << pos);
                float candL = (pos & 32) ? glo1 : glo0;
                float candH = (pos & 32) ? ghi1 : ghi0;
                float pl = __shfl_sync(0xffffffffu, candL, pos & 31);
                float ph = __shfl_sync(0xffffffffu, candH, pos & 31);
                float pw = ph - pl;
                bool q0 = false, q1 = false;
                {
                    float inter = fminf(ph, ghi0) - fmaxf(pl, glo0);
                    if (inter > 0.0f) {
                        float uni = pw + (ghi0 - glo0) - inter;
                        q0 = inter / fmaxf(uni, 1e-8f) > 0.5f;
                    }
                    inter = fminf(ph, ghi1) - fmaxf(pl, glo1);
                    if (inter > 0.0f) {
                        float uni = pw + (ghi1 - glo1) - inter;
                        q1 = inter / fmaxf(uni, 1e-8f) > 0.5f;
                    }
                }
                unsigned b0 = __ballot_sync(0xffffffffu, q0);
                unsigned b1 = __ballot_sync(0xffffffffu, q1);
                at &= ~(((u64)b1 << 32) | (u64)b0);
                at = (pos < 63) ? (at & (~0ull << (pos + 1))) : 0ull;
                if (lane == 0) { keptLo[kt] = pl; keptHi[kt] = ph; }
                kt++;
            }
            if (lane == 0) {
                alive[t] = kept;
                sDLo[(t + 1) & 1] = T0;
                sDHi[(t + 1) & 1] = kt;
                if (kt >= Kq) { sStop = 1; sStopT = t; }
            }
            // prefetch next tile's boxes (keys/lohi are constant)
            if (t + 1 < NTILE) {
                u64 k0 = keys[(t + 1) * 64 + lane];
                u64 k1 = keys[(t + 1) * 64 + lane + 32];
                float2 a0 = lohi[(int)(k0 & 0xffffffffu)];
                float2 a1 = lohi[(int)(k1 & 0xffffffffu)];
                glo0 = a0.x; ghi0 = a0.y; glo1 = a1.x; ghi1 = a1.y;
            }
        } else {
            // background: apply previous delta to strictly-later owned tiles
            const int dLo = sDLo[t & 1], dHi = sDHi[t & 1];
            if (myTile > t && myAlive && dHi > dLo) {
                unsigned killed = 0;
                #pragma unroll
                for (int r = 0; r < PER; r++) {
                    if (myAlive & (1u << r)) {
                        float lo = myLo[r], hi = myHi[r];
                        float wb = hi - lo;
                        for (int s = dLo; s < dHi; s++) {
                            float pl = keptLo[s], ph = keptHi[s];
                            float inter = fminf(ph, hi) - fmaxf(pl, lo);
                            if (inter > 0.0f) {
                                float uni = (ph - pl) + wb - inter;
                                if (inter / fmaxf(uni, 1e-8f) > 0.5f) { killed |= (1u << r); break; }
                            }
                        }
                    }
                }
                if (killed) {
                    myAlive &= ~killed;
                    atomicAnd(&alive[tid >> 4], ~((u64)killed << ((tid & 15) * PER)));
                }
            }
        }
        __syncthreads();
        if (sStop) break;   // exactly K kept found; later tiles cannot matter
    }

    // Tiles past the stop point contribute nothing
    if (tid < NWORD && tid > sStopT) alive[tid] = 0ull;
    __syncthreads();

    // ---------- Phase 5: ranks + emit top-K with NEG padding ----------
    if (tid == 0) {
        int acc = 0;
        #pragma unroll
        for (int w = 0; w < NWORD; w++) { wp[w] = acc; acc += __popcll(alive[w]); }
        wp[NWORD] = acc;
    }
    __syncthreads();
    const int T = wp[NWORD];
    float* o = out + ((size_t)(b * 2 + c)) * Kq * 3;

    const u64 aw = alive[tid >> 4];
    #pragma unroll
    for (int r = 0; r < PER; r++) {
        int p = base + r;
        int bit = p & 63;
        u64 lowmask = (bit == 0) ? 0ull : ((1ull << bit) - 1ull);
        int  kr   = wp[p >> 6] + __popcll(aw & lowmask);
        bool kept = (aw >> bit) & 1ull;
        if (kept) {
            if (kr < Kq) {
                o[kr * 3 + 0] = myLo[r];
                o[kr * 3 + 1] = myHi[r];
                o[kr * 3 + 2] = key_to_score((unsigned)(v[r] >> 32));
            }
        } else {
            int nr = p - kr;                       // non-kept rank (lowest pos first)
            if (T < Kq && nr < Kq - T) {
                int slot = T + nr;
                o[slot * 3 + 0] = myLo[r];
                o[slot * 3 + 1] = myHi[r];
                o[slot * 3 + 2] = NEGV;
            }
        }
    }
}

extern "C" void kernel_launch(void* const* d_in, const int* in_sizes, int n_in,
                              void* d_out, int out_size)
{
    const float* logit  = (const float*)d_in[0];   // [16,2048,3]
    const float* reg    = (const float*)d_in[1];   // [16,2048,6]
    const float* prop   = (const float*)d_in[2];   // [16,2048,2]
    const int*   ishape = (const int*)d_in[3];     // scalar
    float* out = (float*)d_out;                    // [16,2,100,3]

    roiheads_kernel<<<Bq * (Cq - 1), THREADS>>>(logit, reg, prop, ishape, out);
}

// round 7
// speedup vs baseline: 1.3393x; 1.0940x over previous
#include <cuda_runtime.h>
#include <cstdint>

#define Bq 16
#define Nq 2048
#define Cq 3
#define Kq 100
#define THREADS 1024
#define PER (Nq / THREADS)   // 2 contiguous sorted positions per thread
#define NWORD (Nq / 64)      // 32 bitmap words
#define NTILE (Nq / 64)      // 32 tiles; warp w owns tile w
#define KCAP 112
#define NEGV (-1e9f)

typedef unsigned long long u64;

__device__ __forceinline__ unsigned fkey_desc(float f) {
    unsigned u = __float_as_uint(f);
    u = (u & 0x80000000u) ? ~u : (u | 0x80000000u);
    return ~u;
}
__device__ __forceinline__ float key_to_score(unsigned k) {
    unsigned u = ~k;
    u = (u & 0x80000000u) ? (u & 0x7fffffffu) : ~u;
    return __uint_as_float(u);
}

__global__ void __launch_bounds__(THREADS)
roiheads_kernel(const float* __restrict__ logit,   // [B,N,3]
                const float* __restrict__ reg,     // [B,N,6]
                const float* __restrict__ prop,    // [B,N,2]
                const int*   __restrict__ ishape,  // scalar
                float*       __restrict__ out)     // [B,2,K,3]
{
    __shared__ u64    keys[Nq];
    __shared__ float2 lohi[Nq];
    __shared__ float  keptLo[KCAP], keptHi[KCAP];
    __shared__ u64    alive[NWORD];
    __shared__ int    sDLo[2], sDHi[2];
    __shared__ int    sStop, sStopT;
    __shared__ int    wp[NWORD + 1];

    const int b      = blockIdx.x >> 1;
    const int c      = blockIdx.x & 1;
    const int cls    = c + 1;
    const int tid    = threadIdx.x;
    const int lane   = tid & 31;
    const int wid    = tid >> 5;         // warp id == owned tile
    const int base   = tid * PER;        // first owned sorted position

    int ib = ishape[0];
    float img = (ib > 0 && ib < (1 << 24)) ? (float)ib : __int_as_float(ib);

    if (tid < NWORD) alive[tid] = 0ull;
    if (tid == 0) { sDLo[0] = 0; sDHi[0] = 0; sStop = 0; sStopT = NTILE - 1; }

    // ---------- Phase 1: softmax + decode + clip + mask -> keys in regs ----------
    u64 v[PER];
    {
        const float2* lgv = (const float2*)(logit + ((size_t)b * Nq + base) * Cq);
        float2 G0 = lgv[0], G1 = lgv[1], G2 = lgv[2];           // 6 floats
        const float4  P   = *(const float4*)(prop + ((size_t)b * Nq + base) * 2);
        float lg[6] = {G0.x, G0.y, G1.x, G1.y, G2.x, G2.y};
        float pr[4] = {P.x, P.y, P.z, P.w};

        #pragma unroll
        for (int r = 0; r < PER; r++) {
            int j = base + r;
            float l0 = lg[r*3+0], l1 = lg[r*3+1], l2 = lg[r*3+2];
            float m  = fmaxf(l0, fmaxf(l1, l2));
            float e0 = expf(l0 - m), e1 = expf(l1 - m), e2 = expf(l2 - m);
            float s  = ((cls == 1) ? e1 : e2) / (e0 + e1 + e2);

            const float2 dd = *(const float2*)(reg + ((size_t)b * Nq + j) * (2 * Cq) + 2 * cls);
            float dx = dd.x;
            float dw = fminf(dd.y, 4.0f);

            float p0 = pr[r*2+0], p1 = pr[r*2+1];
            float w   = p1 - p0;
            float ctr = p0 + 0.5f * w;
            float pc  = dx * w + ctr;
            float pw  = expf(dw) * w;
            float lo  = fminf(fmaxf(pc - 0.5f * pw, 0.0f), img);
            float hi  = fminf(fmaxf(pc + 0.5f * pw, 0.0f), img);

            bool  valid = ((hi - lo) >= 10.0f) && (s >= 0.05f);
            float ms    = valid ? s : NEGV;

            lohi[j] = make_float2(lo, hi);
            v[r] = ((u64)fkey_desc(ms) << 32) | (unsigned)j;
        }
    }

    // ---------- Phase 2: bitonic sort; smem only for strides >= 64 ----------
    for (int k = 2; k <= Nq; k <<= 1) {
        int j2 = k >> 1;
        if (j2 >= 64) {
            #pragma unroll
            for (int r = 0; r < PER; r++) keys[base + r] = v[r];
            __syncthreads();
            for (; j2 >= 64; j2 >>= 1) {
                #pragma unroll
                for (int rr = 0; rr < PER; rr++) {
                    int i  = tid + rr * THREADS;
                    int ix = i ^ j2;
                    if (ix > i) {
                        bool up = ((i & k) == 0);
                        u64 a = keys[i], bb = keys[ix];
                        if ((a > bb) == up) { keys[i] = bb; keys[ix] = a; }
                    }
                }
                __syncthreads();
            }
            #pragma unroll
            for (int r = 0; r < PER; r++) v[r] = keys[base + r];
        }
        // warp-local strides 32..2 via shuffle (lane delta = j2/2)
        for (; j2 >= 2; j2 >>= 1) {
            int ld = j2 >> 1;
            #pragma unroll
            for (int r = 0; r < PER; r++) {
                u64 other = __shfl_xor_sync(0xffffffffu, v[r], ld);
                int i = base + r;
                bool up    = ((i & k)  == 0);
                bool lower = ((i & j2) == 0);
                bool tmin  = (up == lower);
                u64 mn = (v[r] < other) ? v[r] : other;
                u64 mx = (v[r] < other) ? other : v[r];
                v[r] = tmin ? mn : mx;
            }
        }
        // register-local stride 1
        {
            bool up = ((base & k) == 0);
            u64 a = v[0], bb = v[1];
            if ((a > bb) == up) { v[0] = bb; v[1] = a; }
        }
    }

    // ---------- Phase 3: spill keys; cache owned boxes; alive bitmap ----------
    float myLo[PER], myHi[PER];
    unsigned myAlive = 0;
    #pragma unroll
    for (int r = 0; r < PER; r++) {
        keys[base + r] = v[r];
        int idx = (int)(v[r] & 0xffffffffu);
        float2 lh = lohi[idx];
        myLo[r] = lh.x;
        myHi[r] = lh.y;
        if (key_to_score((unsigned)(v[r] >> 32)) > 0.5f * NEGV)
            myAlive |= (1u << r);
    }
    if (myAlive)
        atomicOr(&alive[wid], (u64)myAlive << (lane * PER));
    __syncthreads();

    // ---------- Phase 4: pipelined tile NMS (1 barrier / tile) ----------
    float glo0 = 0.f, ghi0 = 0.f, glo1 = 0.f, ghi1 = 0.f;
    int kt = 0;
    if (wid == 0) {
        u64 k0 = keys[lane];
        u64 k1 = keys[lane + 32];
        float2 a0 = lohi[(int)(k0 & 0xffffffffu)];
        float2 a1 = lohi[(int)(k1 & 0xffffffffu)];
        glo0 = a0.x; ghi0 = a0.y; glo1 = a1.x; ghi1 = a1.y;
    }

    for (int t = 0; t < NTILE; t++) {
        if (wid == 0) {
            u64 at = alive[t];
            const float w0 = ghi0 - glo0, w1 = ghi1 - glo1;
            // urgent: apply previous tile's kept delta to this tile's boxes
            const int dLo = sDLo[t & 1], dHi = sDHi[t & 1];
            if (at != 0ull && dHi > dLo) {
                bool q0 = false, q1 = false;
                for (int s = dLo; s < dHi; s++) {
                    float pl = keptLo[s], ph = keptHi[s];
                    float pw = ph - pl;
                    float i0 = fminf(ph, ghi0) - fmaxf(pl, glo0);
                    if (i0 > 0.0f) {
                        float uni = pw + w0 - i0;
                        q0 |= (i0 / fmaxf(uni, 1e-8f) > 0.5f);
                    }
                    float i1 = fminf(ph, ghi1) - fmaxf(pl, glo1);
                    if (i1 > 0.0f) {
                        float uni = pw + w1 - i1;
                        q1 |= (i1 / fmaxf(uni, 1e-8f) > 0.5f);
                    }
                }
                unsigned b0 = __ballot_sync(0xffffffffu, q0);
                unsigned b1 = __ballot_sync(0xffffffffu, q1);
                at &= ~(((u64)b1 << 32) | (u64)b0);
            }
            // greedy over the tile, capped at Kq kept total
            const int T0 = kt;
            u64 kept = 0;
            while (at && kt < Kq) {
                int pos = __ffsll((long long)at) - 1;
                kept |= (1ull << pos);
                float candL = (pos & 32) ? glo1 : glo0;
                float candH = (pos & 32) ? ghi1 : ghi0;
                u64 packed = ((u64)__float_as_uint(candH) << 32) | __float_as_uint(candL);
                u64 got = __shfl_sync(0xffffffffu, packed, pos & 31);
                float pl = __uint_as_float((unsigned)(got & 0xffffffffu));
                float ph = __uint_as_float((unsigned)(got >> 32));
                float pw = ph - pl;
                bool q0 = false, q1 = false;
                {
                    float inter = fminf(ph, ghi0) - fmaxf(pl, glo0);
                    if (inter > 0.0f) {
                        float uni = pw + w0 - inter;
                        q0 = inter / fmaxf(uni, 1e-8f) > 0.5f;
                    }
                    inter = fminf(ph, ghi1) - fmaxf(pl, glo1);
                    if (inter > 0.0f) {
                        float uni = pw + w1 - inter;
                        q1 = inter / fmaxf(uni, 1e-8f) > 0.5f;
                    }
                }
                unsigned b0 = __ballot_sync(0xffffffffu, q0);
                unsigned b1 = __ballot_sync(0xffffffffu, q1);
                at &= ~(((u64)b1 << 32) | (u64)b0);
                at = (pos < 63) ? (at & (~0ull << (pos + 1))) : 0ull;
                if (lane == 0) { keptLo[kt] = pl; keptHi[kt] = ph; }
                kt++;
            }
            if (lane == 0) {
                alive[t] = kept;
                sDLo[(t + 1) & 1] = T0;
                sDHi[(t + 1) & 1] = kt;
                if (kt >= Kq) { sStop = 1; sStopT = t; }
            }
            // prefetch next tile's boxes
            if (t + 1 < NTILE) {
                u64 k0 = keys[(t + 1) * 64 + lane];
                u64 k1 = keys[(t + 1) * 64 + lane + 32];
                float2 a0 = lohi[(int)(k0 & 0xffffffffu)];
                float2 a1 = lohi[(int)(k1 & 0xffffffffu)];
                glo0 = a0.x; ghi0 = a0.y; glo1 = a1.x; ghi1 = a1.y;
            }
        } else {
            // background: apply previous delta to strictly-later owned tiles
            const int dLo = sDLo[t & 1], dHi = sDHi[t & 1];
            if (wid > t && myAlive && dHi > dLo) {
                unsigned killed = 0;
                #pragma unroll
                for (int r = 0; r < PER; r++) {
                    if (myAlive & (1u << r)) {
                        float lo = myLo[r], hi = myHi[r];
                        float wb = hi - lo;
                        for (int s = dLo; s < dHi; s++) {
                            float pl = keptLo[s], ph = keptHi[s];
                            float inter = fminf(ph, hi) - fmaxf(pl, lo);
                            if (inter > 0.0f) {
                                float uni = (ph - pl) + wb - inter;
                                if (inter / fmaxf(uni, 1e-8f) > 0.5f) { killed |= (1u << r); break; }
                            }
                        }
                    }
                }
                if (killed) {
                    myAlive &= ~killed;
                    atomicAnd(&alive[wid], ~((u64)killed << (lane * PER)));
                }
            }
        }
        __syncthreads();
        if (sStop) break;   // exactly K kept found; later tiles cannot matter
    }

    if (tid < NWORD && tid > sStopT) alive[tid] = 0ull;
    __syncthreads();

    // ---------- Phase 5: ranks + emit top-K with NEG padding ----------
    if (tid == 0) {
        int acc = 0;
        #pragma unroll
        for (int w = 0; w < NWORD; w++) { wp[w] = acc; acc += __popcll(alive[w]); }
        wp[NWORD] = acc;
    }
    __syncthreads();
    const int T = wp[NWORD];
    float* o = out + ((size_t)(b * 2 + c)) * Kq * 3;

    const u64 aw = alive[wid];
    #pragma unroll
    for (int r = 0; r < PER; r++) {
        int p = base + r;
        int bit = p & 63;
        u64 lowmask = (bit == 0) ? 0ull : ((1ull << bit) - 1ull);
        int  kr   = wp[p >> 6] + __popcll(aw & lowmask);
        bool kept = (aw >> bit) & 1ull;
        if (kept) {
            if (kr < Kq) {
                o[kr * 3 + 0] = myLo[r];
                o[kr * 3 + 1] = myHi[r];
                o[kr * 3 + 2] = key_to_score((unsigned)(v[r] >> 32));
            }
        } else {
            int nr = p - kr;
            if (T < Kq && nr < Kq - T) {
                int slot = T + nr;
                o[slot * 3 + 0] = myLo[r];
                o[slot * 3 + 1] = myHi[r];
                o[slot * 3 + 2] = NEGV;
            }
        }
    }
}

extern "C" void kernel_launch(void* const* d_in, const int* in_sizes, int n_in,
                              void* d_out, int out_size)
{
    const float* logit  = (const float*)d_in[0];   // [16,2048,3]
    const float* reg    = (const float*)d_in[1];   // [16,2048,6]
    const float* prop   = (const float*)d_in[2];   // [16,2048,2]
    const int*   ishape = (const int*)d_in[3];     // scalar
    float* out = (float*)d_out;                    // [16,2,100,3]

    roiheads_kernel<<<Bq * (Cq - 1), THREADS>>>(logit, reg, prop, ishape, out);
}